// round 1
// baseline (speedup 1.0000x reference)
#include <cuda_runtime.h>
#include <cuda_bf16.h>

#define DIM   128
#define BATCH 8192

// Scratch (no allocations allowed in kernel_launch)
__device__ float g_scores[BATCH];
__device__ int   g_is64;

// Detect whether the triple arrays are int64 (odd 32-bit words all zero since
// indices < 500) or int32. Deterministic, reads only positive_triples.
__global__ void detect_dtype_kernel(const int* __restrict__ p) {
    if (threadIdx.x == 0) {
        int is64 = 1;
        #pragma unroll
        for (int i = 0; i < 16; i++)
            if (p[2 * i + 1] != 0) is64 = 0;
        g_is64 = is64;
    }
}

__device__ __forceinline__ float block_sum128(float v, volatile float* sbuf) {
    #pragma unroll
    for (int o = 16; o > 0; o >>= 1)
        v += __shfl_xor_sync(0xffffffffu, v, o);
    int w = threadIdx.x >> 5;
    if ((threadIdx.x & 31) == 0) sbuf[w] = v;
    __syncthreads();
    float s = sbuf[0] + sbuf[1] + sbuf[2] + sbuf[3];
    __syncthreads();
    return s;
}

__global__ void __launch_bounds__(128, 8) score_kernel(
    const void* __restrict__ pos_t,
    const void* __restrict__ neg_t,
    const float* __restrict__ ent,
    const float* __restrict__ rel,
    const float* __restrict__ tm)
{
    const int b = blockIdx.x;
    const int e = threadIdx.x;  // output column 0..127
    const int is64 = g_is64;

    __shared__ float sh[4][DIM];   // h_pos, t_pos, h_neg, t_neg
    __shared__ float sbuf[4];

    long long hp, rp, tp, hn, rn, tn;
    if (is64) {
        const long long* P = (const long long*)pos_t;
        const long long* N = (const long long*)neg_t;
        hp = P[3 * b + 0]; rp = P[3 * b + 1]; tp = P[3 * b + 2];
        hn = N[3 * b + 0]; rn = N[3 * b + 1]; tn = N[3 * b + 2];
    } else {
        const int* P = (const int*)pos_t;
        const int* N = (const int*)neg_t;
        hp = P[3 * b + 0]; rp = P[3 * b + 1]; tp = P[3 * b + 2];
        hn = N[3 * b + 0]; rn = N[3 * b + 1]; tn = N[3 * b + 2];
    }

    sh[0][e] = ent[hp * DIM + e];
    sh[1][e] = ent[tp * DIM + e];
    sh[2][e] = ent[hn * DIM + e];
    sh[3][e] = ent[tn * DIM + e];
    const float rpv = rel[rp * DIM + e];
    const float rnv = rel[rn * DIM + e];
    __syncthreads();

    // h' = h @ Mr  (Mr is [d][e] row-major), same Mr element feeds h and t FMAs
    const float* Mp = tm + rp * (long long)(DIM * DIM) + e;
    const float* Mn = tm + rn * (long long)(DIM * DIM) + e;

    float a_hp = 0.f, a_tp = 0.f, a_hn = 0.f, a_tn = 0.f;
    #pragma unroll 8
    for (int d = 0; d < DIM; d++) {
        const float mp = Mp[d * DIM];
        const float mn = Mn[d * DIM];
        const float h0 = sh[0][d], t0 = sh[1][d];
        const float h1 = sh[2][d], t1 = sh[3][d];
        a_hp = fmaf(h0, mp, a_hp);
        a_tp = fmaf(t0, mp, a_tp);
        a_hn = fmaf(h1, mn, a_hn);
        a_tn = fmaf(t1, mn, a_tn);
    }

    // L2-normalize the six vectors (ref: x / max(||x||, 1e-12))
    float ss;
    ss = block_sum128(a_hp * a_hp, sbuf); const float i_hp = 1.0f / fmaxf(sqrtf(ss), 1e-12f);
    ss = block_sum128(a_tp * a_tp, sbuf); const float i_tp = 1.0f / fmaxf(sqrtf(ss), 1e-12f);
    ss = block_sum128(a_hn * a_hn, sbuf); const float i_hn = 1.0f / fmaxf(sqrtf(ss), 1e-12f);
    ss = block_sum128(a_tn * a_tn, sbuf); const float i_tn = 1.0f / fmaxf(sqrtf(ss), 1e-12f);
    ss = block_sum128(rpv * rpv,   sbuf); const float i_rp = 1.0f / fmaxf(sqrtf(ss), 1e-12f);
    ss = block_sum128(rnv * rnv,   sbuf); const float i_rn = 1.0f / fmaxf(sqrtf(ss), 1e-12f);

    const float sp = block_sum128(fabsf(a_hp * i_hp + rpv * i_rp - a_tp * i_tp), sbuf);
    const float sn = block_sum128(fabsf(a_hn * i_hn + rnv * i_rn - a_tn * i_tn), sbuf);

    if (e == 0)
        g_scores[b] = fmaxf(sp - sn + 1.0f, 0.0f);
}

__global__ void reduce_kernel(float* __restrict__ out) {
    __shared__ float sbuf[8];
    float v = 0.f;
    for (int i = threadIdx.x; i < BATCH; i += 256)
        v += g_scores[i];
    #pragma unroll
    for (int o = 16; o > 0; o >>= 1)
        v += __shfl_xor_sync(0xffffffffu, v, o);
    int w = threadIdx.x >> 5;
    if ((threadIdx.x & 31) == 0) sbuf[w] = v;
    __syncthreads();
    if (threadIdx.x == 0) {
        float s = 0.f;
        #pragma unroll
        for (int i = 0; i < 8; i++) s += sbuf[i];
        out[0] = s * (1.0f / (float)BATCH);
    }
}

extern "C" void kernel_launch(void* const* d_in, const int* in_sizes, int n_in,
                              void* d_out, int out_size) {
    // metadata order: positive_triples, negative_triples, entities, relations, transfer_matrix
    const void*  pos = d_in[0];
    const void*  neg = d_in[1];
    const float* ent = (const float*)d_in[2];
    const float* rel = (const float*)d_in[3];
    const float* tm  = (const float*)d_in[4];

    detect_dtype_kernel<<<1, 32>>>((const int*)pos);
    score_kernel<<<BATCH, 128>>>(pos, neg, ent, rel, tm);
    reduce_kernel<<<1, 256>>>((float*)d_out);
}